// round 10
// baseline (speedup 1.0000x reference)
#include <cuda_runtime.h>
#include <math.h>

#define NGRAPH 1024
#define DIM 64
#define INDIM 25
#define MAXN 100000
#define MAXE 1600000

// ---------------- scratch (device globals; no allocation allowed) ----------
__device__ __align__(16) float g_h0[MAXN * DIM];
__device__ __align__(16) float g_aggr[MAXN * DIM];
__device__ __align__(16) float g_h1[MAXN * DIM];
__device__ __align__(16) int2  g_edge32[MAXE];
__device__ int   g_start[NGRAPH + 1];
__device__ float g_hs[NGRAPH * DIM];
__device__ float g_cs[NGRAPH * DIM];
__device__ float g_qstar[NGRAPH * 2 * DIM];
__device__ float g_Wt[192 * 256];      // transposed LSTM weights [k][r]
__device__ float g_bias[256];          // b_ih + b_hh
__device__ int   g_is64;

// ---------------- helpers ---------------------------------------------------
__device__ __forceinline__ long long ld_idx(const void* p, long long i, int is64) {
    return is64 ? ((const long long*)p)[i] : (long long)((const int*)p)[i];
}
__device__ __forceinline__ float sigm(float x) { return 1.0f / (1.0f + __expf(-x)); }

// ------ fused prep: detect dtype (block 0) + zero state + LSTM transpose ----
__global__ void prep_kernel(const void* batch, int N,
                            const float* __restrict__ W_ih,
                            const float* __restrict__ W_hh,
                            const float* __restrict__ b_ih,
                            const float* __restrict__ b_hh) {
    int i = blockIdx.x * blockDim.x + threadIdx.x;
    // detection: batch sorted in [0,1024); if int64, odd 32-bit words are 0
    if (blockIdx.x == 0) {
        __shared__ int nz;
        if (threadIdx.x == 0) nz = 0;
        __syncthreads();
        int limit = N < 20000 ? N : 20000;
        int cnt = 0;
        for (int k = 1 + 2 * (int)threadIdx.x; k < limit; k += 2 * blockDim.x)
            if (((const int*)batch)[k] != 0) cnt++;
        if (cnt) atomicAdd(&nz, cnt);
        __syncthreads();
        if (threadIdx.x == 0) g_is64 = (nz == 0) ? 1 : 0;
    }
    // zero LSTM state + q_star (must cover every replay)
    if (i < NGRAPH * DIM) { g_hs[i] = 0.0f; g_cs[i] = 0.0f; }
    if (i < NGRAPH * 2 * DIM) g_qstar[i] = 0.0f;
    // transpose LSTM weights
    if (i < 256 * 128) {                       // W_ih: [256][128]
        int r = i >> 7, k = i & 127;
        g_Wt[k * 256 + r] = W_ih[i];
    } else if (i < 256 * 128 + 256 * 64) {     // W_hh: [256][64]
        int j = i - 256 * 128;
        int r = j >> 6, k = j & 63;
        g_Wt[(128 + k) * 256 + r] = W_hh[j];
    }
    if (i < 256) g_bias[i] = b_ih[i] + b_hh[i];
}

// ---------------- per-graph node ranges from sorted batch --------------------
__global__ void offsets_kernel(const void* batch, int N) {
    int n = blockIdx.x * blockDim.x + threadIdx.x;
    if (n >= N) return;
    int is64 = g_is64;
    int b = (int)ld_idx(batch, n, is64);
    if (n == 0) {
        for (int g = 0; g <= b; g++) g_start[g] = 0;
    } else {
        int prev = (int)ld_idx(batch, n - 1, is64);
        if (prev != b)
            for (int g = prev + 1; g <= b; g++) g_start[g] = n;
    }
    if (n == N - 1)
        for (int g = b + 1; g <= NGRAPH; g++) g_start[g] = N;
}

// ---------------- edge index pre-conversion to packed int2 ------------------
__global__ void conv_edge_kernel(const void* __restrict__ edge, long long E) {
    long long e = (long long)blockIdx.x * blockDim.x + threadIdx.x;
    if (e >= E) return;
    int is64 = g_is64;
    int s = (int)ld_idx(edge, e, is64);
    int d = (int)ld_idx(edge, E + e, is64);
    g_edge32[e] = make_int2(s, d);
}

// ------ h0 = relu(x @ lin0_W + b); aggr initialized to h0; 32 nodes/block ---
__global__ void lin0_kernel(const float* __restrict__ x,
                            const float* __restrict__ W,
                            const float* __restrict__ b, int N) {
    __shared__ float sW[INDIM * DIM];
    __shared__ float sx[32][INDIM];
    int tid = threadIdx.x;
    for (int i = tid; i < INDIM * DIM; i += 256) sW[i] = W[i];
    int node0 = blockIdx.x * 32;
    long long xbase = (long long)node0 * INDIM;
    int navail = N - node0; if (navail > 32) navail = 32;
    int tot = navail * INDIM;
    for (int i = tid; i < tot; i += 256)
        sx[i / INDIM][i % INDIM] = x[xbase + i];
    __syncthreads();
    int c = tid & 63;
    int ng = tid >> 6;                      // node group 0..3 (8 nodes each)
    float bc = b[c];
    float acc[8];
#pragma unroll
    for (int j = 0; j < 8; j++) acc[j] = bc;
#pragma unroll
    for (int k = 0; k < INDIM; k++) {
        float w = sW[k * DIM + c];
#pragma unroll
        for (int j = 0; j < 8; j++) acc[j] += sx[ng * 8 + j][k] * w;
    }
#pragma unroll
    for (int j = 0; j < 8; j++) {
        int n = node0 + ng * 8 + j;
        if (n < N) {
            float v = fmaxf(acc[j], 0.0f);
            long long o = (long long)n * DIM + c;
            g_h0[o] = v;
            g_aggr[o] = v;
        }
    }
}

// ------- edge scatter: 8 threads/edge, 2 independent RED.128 each -----------
__global__ void scatter_kernel(long long E) {
    long long t = (long long)blockIdx.x * blockDim.x + threadIdx.x;
    if (t >= E * 8) return;
    long long e = t >> 3;
    int j = (int)(t & 7);                     // 32-byte chunk index
    int2 sd = g_edge32[e];                    // broadcast among 8 threads
    const float4* s4 = (const float4*)&g_h0[(long long)sd.x * DIM];
    float4 v0 = s4[2 * j];
    float4 v1 = s4[2 * j + 1];
    float* dst = &g_aggr[(long long)sd.y * DIM + j * 8];
    unsigned long long a0 = (unsigned long long)__cvta_generic_to_global(dst);
    unsigned long long a1 = a0 + 16;
    asm volatile("red.global.add.v4.f32 [%0], {%1, %2, %3, %4};"
                 :: "l"(a0), "f"(v0.x), "f"(v0.y), "f"(v0.z), "f"(v0.w) : "memory");
    asm volatile("red.global.add.v4.f32 [%0], {%1, %2, %3, %4};"
                 :: "l"(a1), "f"(v1.x), "f"(v1.y), "f"(v1.z), "f"(v1.w) : "memory");
}

// ------- h1 = relu(aggr @ gin_W + b); 32 nodes/block, reg-blocked ------------
__global__ __launch_bounds__(256) void gin_kernel(
        const float* __restrict__ W, const float* __restrict__ b, int N) {
    __shared__ float sW[DIM * DIM];        // 16 KB
    __shared__ float srow[32][DIM];        // 8 KB
    int tid = threadIdx.x;
    for (int i = tid; i < DIM * DIM; i += 256) sW[i] = W[i];
    int node0 = blockIdx.x * 32;
    int navail = N - node0; if (navail > 32) navail = 32;
    int tot4 = navail * (DIM / 4);
    long long abase = (long long)node0 * DIM;
    for (int i = tid; i < tot4; i += 256) {
        float4 v = *(const float4*)&g_aggr[abase + i * 4];
        *(float4*)&srow[i / 16][(i % 16) * 4] = v;
    }
    __syncthreads();
    int p  = tid >> 4;               // 0..15
    int c4 = (tid & 15) * 4;         // 0,4,...,60
    float acc0[4], acc1[4];
#pragma unroll
    for (int j = 0; j < 4; j++) { acc0[j] = b[c4 + j]; acc1[j] = acc0[j]; }
#pragma unroll 4
    for (int k0 = 0; k0 < DIM; k0 += 4) {
        float4 ra = *(const float4*)&srow[p][k0];
        float4 rb = *(const float4*)&srow[p + 16][k0];
#pragma unroll
        for (int kk = 0; kk < 4; kk++) {
            float4 wv = *(const float4*)&sW[(k0 + kk) * DIM + c4];
            float rav = (kk == 0) ? ra.x : (kk == 1) ? ra.y : (kk == 2) ? ra.z : ra.w;
            float rbv = (kk == 0) ? rb.x : (kk == 1) ? rb.y : (kk == 2) ? rb.z : rb.w;
            acc0[0] += rav * wv.x; acc0[1] += rav * wv.y;
            acc0[2] += rav * wv.z; acc0[3] += rav * wv.w;
            acc1[0] += rbv * wv.x; acc1[1] += rbv * wv.y;
            acc1[2] += rbv * wv.z; acc1[3] += rbv * wv.w;
        }
    }
    int nodeA = node0 + p, nodeB = node0 + p + 16;
    if (nodeA < N) {
        float4 o = make_float4(fmaxf(acc0[0], 0.f), fmaxf(acc0[1], 0.f),
                               fmaxf(acc0[2], 0.f), fmaxf(acc0[3], 0.f));
        *(float4*)&g_h1[(long long)nodeA * DIM + c4] = o;
    }
    if (nodeB < N) {
        float4 o = make_float4(fmaxf(acc1[0], 0.f), fmaxf(acc1[1], 0.f),
                               fmaxf(acc1[2], 0.f), fmaxf(acc1[3], 0.f));
        *(float4*)&g_h1[(long long)nodeB * DIM + c4] = o;
    }
}

// ---------------- LSTM cell, 16 graphs/block, coalesced transposed weights ---
__global__ void lstm_kernel() {
    __shared__ float s[16 * 192];
    __shared__ float gates[16 * 256];
    int tid = threadIdx.x;
    int gb = blockIdx.x * 16;
    for (int i = tid; i < 16 * 192; i += 256) {
        int g = i / 192, k = i % 192;
        s[i] = (k < 128) ? g_qstar[(gb + g) * 128 + k]
                         : g_hs[(gb + g) * 64 + (k - 128)];
    }
    __syncthreads();
    int r = tid;
    float acc[16];
    float bsum = g_bias[r];
#pragma unroll
    for (int g = 0; g < 16; g++) acc[g] = bsum;
    for (int k = 0; k < 192; k++) {
        float wv = g_Wt[k * 256 + r];          // coalesced
#pragma unroll
        for (int g = 0; g < 16; g++) acc[g] += wv * s[g * 192 + k];
    }
#pragma unroll
    for (int g = 0; g < 16; g++) gates[g * 256 + r] = acc[g];
    __syncthreads();
    for (int cell = tid; cell < 16 * 64; cell += 256) {
        int g = cell >> 6, u = cell & 63;
        int gg = gb + g;
        float iv = gates[g * 256 + u];
        float fv = gates[g * 256 + 64 + u];
        float gv = gates[g * 256 + 128 + u];
        float ov = gates[g * 256 + 192 + u];
        float c_old = g_cs[gg * 64 + u];
        float c_new = sigm(fv) * c_old + sigm(iv) * tanhf(gv);
        float h_new = sigm(ov) * tanhf(c_new);
        g_cs[gg * 64 + u] = c_new;
        g_hs[gg * 64 + u] = h_new;
        g_qstar[gg * 128 + u] = h_new;
    }
}

// -------- per-graph softmax attention, single pass (online softmax) ----------
__global__ void attn_kernel() {
    __shared__ float qsh[DIM];
    __shared__ float rsh[4][DIM];
    __shared__ float dsh[4];
    __shared__ float msh[4];
    int g = blockIdx.x;
    int tid = threadIdx.x;
    int warp = tid >> 5, lane = tid & 31;
    if (tid < DIM) qsh[tid] = g_hs[g * DIM + tid];
    __syncthreads();
    int s0 = g_start[g], s1 = g_start[g + 1];
    float qa = qsh[2 * lane], qb = qsh[2 * lane + 1];
    float m = -1e30f, d = 0.0f, rx = 0.0f, ry = 0.0f;
    for (int n = s0 + warp; n < s1; n += 4) {
        float2 hv = *(const float2*)&g_h1[(long long)n * DIM + 2 * lane];
        float p = hv.x * qa + hv.y * qb;
#pragma unroll
        for (int off = 16; off > 0; off >>= 1) p += __shfl_xor_sync(0xFFFFFFFF, p, off);
        float mn = fmaxf(m, p);
        float sc = __expf(m - mn);
        float wt = __expf(p - mn);
        d  = d * sc + wt;
        rx = rx * sc + wt * hv.x;
        ry = ry * sc + wt * hv.y;
        m = mn;
    }
    rsh[warp][2 * lane]     = rx;
    rsh[warp][2 * lane + 1] = ry;
    if (lane == 0) { dsh[warp] = d; msh[warp] = m; }
    __syncthreads();
    if (tid < DIM) {
        float gm = fmaxf(fmaxf(msh[0], msh[1]), fmaxf(msh[2], msh[3]));
        float r = 0.0f, den = 0.0f;
#pragma unroll
        for (int w = 0; w < 4; w++) {
            float sc = (msh[w] > -1e29f) ? __expf(msh[w] - gm) : 0.0f;
            r   += rsh[w][tid] * sc;
            den += dsh[w] * sc;
        }
        if (den == 0.0f) den = 1.0f;
        g_qstar[g * 128 + DIM + tid] = r / den;
    }
}

// ---------------- head: out = relu(q_star@lin1+b1) @ lin2 + b2 --------------
__global__ void head_kernel(const float* __restrict__ lin1_W,
                            const float* __restrict__ lin1_b,
                            const float* __restrict__ lin2_W,
                            const float* __restrict__ lin2_b,
                            float* __restrict__ out) {
    __shared__ float qs[128];
    __shared__ float red[64];
    int g = blockIdx.x;
    int t = threadIdx.x;
    qs[t] = g_qstar[g * 128 + t];
    qs[t + 64] = g_qstar[g * 128 + t + 64];
    __syncthreads();
    float acc = lin1_b[t];
#pragma unroll 8
    for (int k = 0; k < 128; k++) acc += qs[k] * lin1_W[k * 64 + t];
    acc = fmaxf(acc, 0.0f);
    red[t] = acc * lin2_W[t];
    __syncthreads();
    if (t < 32) {
        float v = red[t] + red[t + 32];
#pragma unroll
        for (int off = 16; off > 0; off >>= 1) v += __shfl_xor_sync(0xFFFFFFFF, v, off);
        if (t == 0) out[g] = v + lin2_b[0];
    }
}

// ---------------- launch ------------------------------------------------------
extern "C" void kernel_launch(void* const* d_in, const int* in_sizes, int n_in,
                              void* d_out, int out_size) {
    const float* x      = (const float*)d_in[0];
    const void*  edge   = d_in[1];
    const void*  batch  = d_in[2];
    const float* lin0_W = (const float*)d_in[3];
    const float* lin0_b = (const float*)d_in[4];
    const float* gin_W  = (const float*)d_in[5];
    const float* gin_b  = (const float*)d_in[6];
    const float* W_ih   = (const float*)d_in[7];
    const float* W_hh   = (const float*)d_in[8];
    const float* b_ih   = (const float*)d_in[9];
    const float* b_hh   = (const float*)d_in[10];
    const float* lin1_W = (const float*)d_in[11];
    const float* lin1_b = (const float*)d_in[12];
    const float* lin2_W = (const float*)d_in[13];
    const float* lin2_b = (const float*)d_in[14];
    float* out = (float*)d_out;

    int N = in_sizes[0] / INDIM;
    long long E = (long long)in_sizes[1] / 2;

    prep_kernel<<<(NGRAPH * 2 * DIM + 255) / 256, 256>>>(batch, N, W_ih, W_hh, b_ih, b_hh);
    offsets_kernel<<<(N + 255) / 256, 256>>>(batch, N);
    conv_edge_kernel<<<(unsigned)((E + 255) / 256), 256>>>(edge, E);
    lin0_kernel<<<(N + 31) / 32, 256>>>(x, lin0_W, lin0_b, N);
    scatter_kernel<<<(unsigned)((E * 8 + 255) / 256), 256>>>(E);
    gin_kernel<<<(N + 31) / 32, 256>>>(gin_W, gin_b, N);
    for (int step = 0; step < 3; step++) {
        lstm_kernel<<<NGRAPH / 16, 256>>>();
        attn_kernel<<<NGRAPH, 128>>>();
    }
    head_kernel<<<NGRAPH, 64>>>(lin1_W, lin1_b, lin2_W, lin2_b, out);
}

// round 11
// speedup vs baseline: 1.0722x; 1.0722x over previous
#include <cuda_runtime.h>
#include <math.h>

#define NGRAPH 1024
#define DIM 64
#define INDIM 25
#define MAXN 100000

// ---------------- scratch (device globals; no allocation allowed) ----------
__device__ __align__(16) float g_h0[MAXN * DIM];
__device__ __align__(16) float g_aggr[MAXN * DIM];
__device__ __align__(16) float g_h1[MAXN * DIM];
__device__ int   g_start[NGRAPH + 1];
__device__ float g_hs[NGRAPH * DIM];
__device__ float g_cs[NGRAPH * DIM];
__device__ float g_qstar[NGRAPH * 2 * DIM];
__device__ float g_Wt[192 * 256];      // transposed LSTM weights [k][r]
__device__ float g_bias[256];          // b_ih + b_hh
__device__ int   g_is64;

// ---------------- helpers ---------------------------------------------------
__device__ __forceinline__ long long ld_idx(const void* p, long long i, int is64) {
    return is64 ? ((const long long*)p)[i] : (long long)((const int*)p)[i];
}
__device__ __forceinline__ float sigm(float x) { return 1.0f / (1.0f + __expf(-x)); }

// ------ fused prep: detect dtype (block 0) + zero state + LSTM transpose ----
__global__ void prep_kernel(const void* batch, int N,
                            const float* __restrict__ W_ih,
                            const float* __restrict__ W_hh,
                            const float* __restrict__ b_ih,
                            const float* __restrict__ b_hh) {
    int i = blockIdx.x * blockDim.x + threadIdx.x;
    if (blockIdx.x == 0) {
        __shared__ int nz;
        if (threadIdx.x == 0) nz = 0;
        __syncthreads();
        int limit = N < 20000 ? N : 20000;
        int cnt = 0;
        for (int k = 1 + 2 * (int)threadIdx.x; k < limit; k += 2 * blockDim.x)
            if (((const int*)batch)[k] != 0) cnt++;
        if (cnt) atomicAdd(&nz, cnt);
        __syncthreads();
        if (threadIdx.x == 0) g_is64 = (nz == 0) ? 1 : 0;
    }
    if (i < NGRAPH * DIM) { g_hs[i] = 0.0f; g_cs[i] = 0.0f; }
    if (i < NGRAPH * 2 * DIM) g_qstar[i] = 0.0f;
    if (i < 256 * 128) {                       // W_ih: [256][128]
        int r = i >> 7, k = i & 127;
        g_Wt[k * 256 + r] = W_ih[i];
    } else if (i < 256 * 128 + 256 * 64) {     // W_hh: [256][64]
        int j = i - 256 * 128;
        int r = j >> 6, k = j & 63;
        g_Wt[(128 + k) * 256 + r] = W_hh[j];
    }
    if (i < 256) g_bias[i] = b_ih[i] + b_hh[i];
}

// ---------------- per-graph node ranges from sorted batch --------------------
__global__ void offsets_kernel(const void* batch, int N) {
    int n = blockIdx.x * blockDim.x + threadIdx.x;
    if (n >= N) return;
    int is64 = g_is64;
    int b = (int)ld_idx(batch, n, is64);
    if (n == 0) {
        for (int g = 0; g <= b; g++) g_start[g] = 0;
    } else {
        int prev = (int)ld_idx(batch, n - 1, is64);
        if (prev != b)
            for (int g = prev + 1; g <= b; g++) g_start[g] = n;
    }
    if (n == N - 1)
        for (int g = b + 1; g <= NGRAPH; g++) g_start[g] = N;
}

// ------ h0 = relu(x @ lin0_W + b); aggr := h0; 32 nodes/block ---------------
// x tile transposed in smem so per-k node loads are 2x LDS.128 (not 8 scalar).
__global__ void lin0_kernel(const float* __restrict__ x,
                            const float* __restrict__ W,
                            const float* __restrict__ b, int N) {
    __shared__ float sW[INDIM * DIM];       // 6.4 KB
    __shared__ float sxT[INDIM][32];        // transposed tile: [k][node]
    int tid = threadIdx.x;
    for (int i = tid; i < INDIM * DIM; i += 256) sW[i] = W[i];
    int node0 = blockIdx.x * 32;
    long long xbase = (long long)node0 * INDIM;
    int navail = N - node0; if (navail > 32) navail = 32;
    int tot = navail * INDIM;
    for (int i = tid; i < tot; i += 256) {
        float v = x[xbase + i];             // coalesced read
        sxT[i % INDIM][i / INDIM] = v;      // transposed write
    }
    __syncthreads();
    int c = tid & 63;
    int ng = tid >> 6;                      // node group 0..3 (8 nodes each)
    float bc = b[c];
    float acc[8];
#pragma unroll
    for (int j = 0; j < 8; j++) acc[j] = bc;
#pragma unroll
    for (int k = 0; k < INDIM; k++) {
        float w = sW[k * DIM + c];
        float4 na = *(const float4*)&sxT[k][ng * 8];      // 4 nodes
        float4 nb = *(const float4*)&sxT[k][ng * 8 + 4];  // 4 nodes
        acc[0] += na.x * w; acc[1] += na.y * w;
        acc[2] += na.z * w; acc[3] += na.w * w;
        acc[4] += nb.x * w; acc[5] += nb.y * w;
        acc[6] += nb.z * w; acc[7] += nb.w * w;
    }
#pragma unroll
    for (int j = 0; j < 8; j++) {
        int n = node0 + ng * 8 + j;
        if (n < N) {
            float v = fmaxf(acc[j], 0.0f);
            long long o = (long long)n * DIM + c;
            g_h0[o] = v;
            g_aggr[o] = v;
        }
    }
}

// ---------------- edge scatter: aggr[dst] += h0[src] (vector RED) -----------
// R9-proven form: 16 threads/edge, one RED.128 each, coalesced row access.
__global__ void scatter_kernel(const void* __restrict__ edge, long long E) {
    long long t = (long long)blockIdx.x * blockDim.x + threadIdx.x;
    long long total = E * 16;
    if (t >= total) return;
    int is64 = g_is64;
    long long e = t >> 4;
    int q = (int)(t & 15);
    long long s = ld_idx(edge, e, is64);
    long long d = ld_idx(edge, E + e, is64);
    float4 v = *(const float4*)&g_h0[s * DIM + q * 4];
    float* dst = &g_aggr[d * DIM + q * 4];
    unsigned long long gaddr = (unsigned long long)__cvta_generic_to_global(dst);
    asm volatile("red.global.add.v4.f32 [%0], {%1, %2, %3, %4};"
                 :: "l"(gaddr), "f"(v.x), "f"(v.y), "f"(v.z), "f"(v.w)
                 : "memory");
}

// ------- h1 = relu(aggr @ gin_W + b); 32 nodes/block, reg-blocked ------------
__global__ __launch_bounds__(256) void gin_kernel(
        const float* __restrict__ W, const float* __restrict__ b, int N) {
    __shared__ float sW[DIM * DIM];        // 16 KB
    __shared__ float srow[32][DIM];        // 8 KB
    int tid = threadIdx.x;
    for (int i = tid; i < DIM * DIM; i += 256) sW[i] = W[i];
    int node0 = blockIdx.x * 32;
    int navail = N - node0; if (navail > 32) navail = 32;
    int tot4 = navail * (DIM / 4);
    long long abase = (long long)node0 * DIM;
    for (int i = tid; i < tot4; i += 256) {
        float4 v = *(const float4*)&g_aggr[abase + i * 4];
        *(float4*)&srow[i / 16][(i % 16) * 4] = v;
    }
    __syncthreads();
    int p  = tid >> 4;               // 0..15
    int c4 = (tid & 15) * 4;         // 0,4,...,60
    float acc0[4], acc1[4];
#pragma unroll
    for (int j = 0; j < 4; j++) { acc0[j] = b[c4 + j]; acc1[j] = acc0[j]; }
#pragma unroll 4
    for (int k0 = 0; k0 < DIM; k0 += 4) {
        float4 ra = *(const float4*)&srow[p][k0];
        float4 rb = *(const float4*)&srow[p + 16][k0];
#pragma unroll
        for (int kk = 0; kk < 4; kk++) {
            float4 wv = *(const float4*)&sW[(k0 + kk) * DIM + c4];
            float rav = (kk == 0) ? ra.x : (kk == 1) ? ra.y : (kk == 2) ? ra.z : ra.w;
            float rbv = (kk == 0) ? rb.x : (kk == 1) ? rb.y : (kk == 2) ? rb.z : rb.w;
            acc0[0] += rav * wv.x; acc0[1] += rav * wv.y;
            acc0[2] += rav * wv.z; acc0[3] += rav * wv.w;
            acc1[0] += rbv * wv.x; acc1[1] += rbv * wv.y;
            acc1[2] += rbv * wv.z; acc1[3] += rbv * wv.w;
        }
    }
    int nodeA = node0 + p, nodeB = node0 + p + 16;
    if (nodeA < N) {
        float4 o = make_float4(fmaxf(acc0[0], 0.f), fmaxf(acc0[1], 0.f),
                               fmaxf(acc0[2], 0.f), fmaxf(acc0[3], 0.f));
        *(float4*)&g_h1[(long long)nodeA * DIM + c4] = o;
    }
    if (nodeB < N) {
        float4 o = make_float4(fmaxf(acc1[0], 0.f), fmaxf(acc1[1], 0.f),
                               fmaxf(acc1[2], 0.f), fmaxf(acc1[3], 0.f));
        *(float4*)&g_h1[(long long)nodeB * DIM + c4] = o;
    }
}

// ---------------- LSTM cell, 16 graphs/block, coalesced transposed weights ---
__global__ void lstm_kernel() {
    __shared__ float s[16 * 192];
    __shared__ float gates[16 * 256];
    int tid = threadIdx.x;
    int gb = blockIdx.x * 16;
    for (int i = tid; i < 16 * 192; i += 256) {
        int g = i / 192, k = i % 192;
        s[i] = (k < 128) ? g_qstar[(gb + g) * 128 + k]
                         : g_hs[(gb + g) * 64 + (k - 128)];
    }
    __syncthreads();
    int r = tid;
    float acc[16];
    float bsum = g_bias[r];
#pragma unroll
    for (int g = 0; g < 16; g++) acc[g] = bsum;
    for (int k = 0; k < 192; k++) {
        float wv = g_Wt[k * 256 + r];          // coalesced
#pragma unroll
        for (int g = 0; g < 16; g++) acc[g] += wv * s[g * 192 + k];
    }
#pragma unroll
    for (int g = 0; g < 16; g++) gates[g * 256 + r] = acc[g];
    __syncthreads();
    for (int cell = tid; cell < 16 * 64; cell += 256) {
        int g = cell >> 6, u = cell & 63;
        int gg = gb + g;
        float iv = gates[g * 256 + u];
        float fv = gates[g * 256 + 64 + u];
        float gv = gates[g * 256 + 128 + u];
        float ov = gates[g * 256 + 192 + u];
        float c_old = g_cs[gg * 64 + u];
        float c_new = sigm(fv) * c_old + sigm(iv) * tanhf(gv);
        float h_new = sigm(ov) * tanhf(c_new);
        g_cs[gg * 64 + u] = c_new;
        g_hs[gg * 64 + u] = h_new;
        g_qstar[gg * 128 + u] = h_new;
    }
}

// -------- per-graph softmax attention, single pass (online softmax) ----------
__global__ void attn_kernel() {
    __shared__ float qsh[DIM];
    __shared__ float rsh[4][DIM];
    __shared__ float dsh[4];
    __shared__ float msh[4];
    int g = blockIdx.x;
    int tid = threadIdx.x;
    int warp = tid >> 5, lane = tid & 31;
    if (tid < DIM) qsh[tid] = g_hs[g * DIM + tid];
    __syncthreads();
    int s0 = g_start[g], s1 = g_start[g + 1];
    float qa = qsh[2 * lane], qb = qsh[2 * lane + 1];
    float m = -1e30f, d = 0.0f, rx = 0.0f, ry = 0.0f;
    for (int n = s0 + warp; n < s1; n += 4) {
        float2 hv = *(const float2*)&g_h1[(long long)n * DIM + 2 * lane];
        float p = hv.x * qa + hv.y * qb;
#pragma unroll
        for (int off = 16; off > 0; off >>= 1) p += __shfl_xor_sync(0xFFFFFFFF, p, off);
        float mn = fmaxf(m, p);
        float sc = __expf(m - mn);
        float wt = __expf(p - mn);
        d  = d * sc + wt;
        rx = rx * sc + wt * hv.x;
        ry = ry * sc + wt * hv.y;
        m = mn;
    }
    rsh[warp][2 * lane]     = rx;
    rsh[warp][2 * lane + 1] = ry;
    if (lane == 0) { dsh[warp] = d; msh[warp] = m; }
    __syncthreads();
    if (tid < DIM) {
        float gm = fmaxf(fmaxf(msh[0], msh[1]), fmaxf(msh[2], msh[3]));
        float r = 0.0f, den = 0.0f;
#pragma unroll
        for (int w = 0; w < 4; w++) {
            float sc = (msh[w] > -1e29f) ? __expf(msh[w] - gm) : 0.0f;
            r   += rsh[w][tid] * sc;
            den += dsh[w] * sc;
        }
        if (den == 0.0f) den = 1.0f;
        g_qstar[g * 128 + DIM + tid] = r / den;
    }
}

// ---------------- head: out = relu(q_star@lin1+b1) @ lin2 + b2 --------------
__global__ void head_kernel(const float* __restrict__ lin1_W,
                            const float* __restrict__ lin1_b,
                            const float* __restrict__ lin2_W,
                            const float* __restrict__ lin2_b,
                            float* __restrict__ out) {
    __shared__ float qs[128];
    __shared__ float red[64];
    int g = blockIdx.x;
    int t = threadIdx.x;
    qs[t] = g_qstar[g * 128 + t];
    qs[t + 64] = g_qstar[g * 128 + t + 64];
    __syncthreads();
    float acc = lin1_b[t];
#pragma unroll 8
    for (int k = 0; k < 128; k++) acc += qs[k] * lin1_W[k * 64 + t];
    acc = fmaxf(acc, 0.0f);
    red[t] = acc * lin2_W[t];
    __syncthreads();
    if (t < 32) {
        float v = red[t] + red[t + 32];
#pragma unroll
        for (int off = 16; off > 0; off >>= 1) v += __shfl_xor_sync(0xFFFFFFFF, v, off);
        if (t == 0) out[g] = v + lin2_b[0];
    }
}

// ---------------- launch ------------------------------------------------------
extern "C" void kernel_launch(void* const* d_in, const int* in_sizes, int n_in,
                              void* d_out, int out_size) {
    const float* x      = (const float*)d_in[0];
    const void*  edge   = d_in[1];
    const void*  batch  = d_in[2];
    const float* lin0_W = (const float*)d_in[3];
    const float* lin0_b = (const float*)d_in[4];
    const float* gin_W  = (const float*)d_in[5];
    const float* gin_b  = (const float*)d_in[6];
    const float* W_ih   = (const float*)d_in[7];
    const float* W_hh   = (const float*)d_in[8];
    const float* b_ih   = (const float*)d_in[9];
    const float* b_hh   = (const float*)d_in[10];
    const float* lin1_W = (const float*)d_in[11];
    const float* lin1_b = (const float*)d_in[12];
    const float* lin2_W = (const float*)d_in[13];
    const float* lin2_b = (const float*)d_in[14];
    float* out = (float*)d_out;

    int N = in_sizes[0] / INDIM;
    long long E = (long long)in_sizes[1] / 2;

    prep_kernel<<<(NGRAPH * 2 * DIM + 255) / 256, 256>>>(batch, N, W_ih, W_hh, b_ih, b_hh);
    offsets_kernel<<<(N + 255) / 256, 256>>>(batch, N);
    lin0_kernel<<<(N + 31) / 32, 256>>>(x, lin0_W, lin0_b, N);
    long long sc_threads = E * 16;
    scatter_kernel<<<(unsigned)((sc_threads + 255) / 256), 256>>>(edge, E);
    gin_kernel<<<(N + 31) / 32, 256>>>(gin_W, gin_b, N);
    for (int step = 0; step < 3; step++) {
        lstm_kernel<<<NGRAPH / 16, 256>>>();
        attn_kernel<<<NGRAPH, 128>>>();
    }
    head_kernel<<<NGRAPH, 64>>>(lin1_W, lin1_b, lin2_W, lin2_b, out);
}

// round 16
// speedup vs baseline: 1.2846x; 1.1981x over previous
#include <cuda_runtime.h>
#include <math.h>

#define NGRAPH 1024
#define DIM 64
#define INDIM 25
#define MAXN 100000

// ---------------- scratch (device globals; no allocation allowed) ----------
__device__ __align__(16) float g_h0[MAXN * DIM];
__device__ __align__(16) float g_aggr[MAXN * DIM];
__device__ __align__(16) float g_h1[MAXN * DIM];
__device__ int   g_start[NGRAPH + 1];
__device__ float g_hs[NGRAPH * DIM];
__device__ float g_cs[NGRAPH * DIM];
__device__ float g_qstar[NGRAPH * 2 * DIM];
__device__ __align__(16) float g_W4[48 * 1024];  // LSTM W packed [k/4][r][4]
__device__ float g_bias[256];                    // b_ih + b_hh
__device__ int   g_is64;

// ---------------- helpers ---------------------------------------------------
__device__ __forceinline__ long long ld_idx(const void* p, long long i, int is64) {
    return is64 ? ((const long long*)p)[i] : (long long)((const int*)p)[i];
}
__device__ __forceinline__ float sigm(float x) { return 1.0f / (1.0f + __expf(-x)); }

// ------ fused prep: detect dtype (block 0) + zero state + LSTM weight pack --
__global__ void prep_kernel(const void* batch, int N,
                            const float* __restrict__ W_ih,
                            const float* __restrict__ W_hh,
                            const float* __restrict__ b_ih,
                            const float* __restrict__ b_hh) {
    int i = blockIdx.x * blockDim.x + threadIdx.x;
    if (blockIdx.x == 0) {
        __shared__ int nz;
        if (threadIdx.x == 0) nz = 0;
        __syncthreads();
        int limit = N < 20000 ? N : 20000;
        int cnt = 0;
        for (int k = 1 + 2 * (int)threadIdx.x; k < limit; k += 2 * blockDim.x)
            if (((const int*)batch)[k] != 0) cnt++;
        if (cnt) atomicAdd(&nz, cnt);
        __syncthreads();
        if (threadIdx.x == 0) g_is64 = (nz == 0) ? 1 : 0;
    }
    if (i < NGRAPH * DIM) { g_hs[i] = 0.0f; g_cs[i] = 0.0f; }
    if (i < NGRAPH * 2 * DIM) g_qstar[i] = 0.0f;
    // pack LSTM weights: g_W4[(k>>2)*1024 + r*4 + (k&3)]
    if (i < 256 * 128) {                       // W_ih: [256][128] -> k in [0,128)
        int r = i >> 7, k = i & 127;
        g_W4[(k >> 2) * 1024 + r * 4 + (k & 3)] = W_ih[i];
    } else if (i < 256 * 128 + 256 * 64) {     // W_hh: [256][64] -> k in [128,192)
        int j = i - 256 * 128;
        int r = j >> 6, k = 128 + (j & 63);
        g_W4[(k >> 2) * 1024 + r * 4 + (k & 3)] = W_hh[j];
    }
    if (i < 256) g_bias[i] = b_ih[i] + b_hh[i];
}

// ---------------- per-graph node ranges from sorted batch --------------------
__global__ void offsets_kernel(const void* batch, int N) {
    int n = blockIdx.x * blockDim.x + threadIdx.x;
    if (n >= N) return;
    int is64 = g_is64;
    int b = (int)ld_idx(batch, n, is64);
    if (n == 0) {
        for (int g = 0; g <= b; g++) g_start[g] = 0;
    } else {
        int prev = (int)ld_idx(batch, n - 1, is64);
        if (prev != b)
            for (int g = prev + 1; g <= b; g++) g_start[g] = n;
    }
    if (n == N - 1)
        for (int g = b + 1; g <= NGRAPH; g++) g_start[g] = N;
}

// ------ h0 = relu(x @ lin0_W + b); aggr := h0; 32 nodes/block ---------------
__global__ void lin0_kernel(const float* __restrict__ x,
                            const float* __restrict__ W,
                            const float* __restrict__ b, int N) {
    __shared__ float sW[INDIM * DIM];       // 6.4 KB
    __shared__ float sxT[INDIM][32];        // transposed tile: [k][node]
    int tid = threadIdx.x;
    for (int i = tid; i < INDIM * DIM; i += 256) sW[i] = W[i];
    int node0 = blockIdx.x * 32;
    long long xbase = (long long)node0 * INDIM;
    int navail = N - node0; if (navail > 32) navail = 32;
    int tot = navail * INDIM;
    for (int i = tid; i < tot; i += 256) {
        float v = x[xbase + i];
        sxT[i % INDIM][i / INDIM] = v;
    }
    __syncthreads();
    int c = tid & 63;
    int ng = tid >> 6;
    float bc = b[c];
    float acc[8];
#pragma unroll
    for (int j = 0; j < 8; j++) acc[j] = bc;
#pragma unroll
    for (int k = 0; k < INDIM; k++) {
        float w = sW[k * DIM + c];
        float4 na = *(const float4*)&sxT[k][ng * 8];
        float4 nb = *(const float4*)&sxT[k][ng * 8 + 4];
        acc[0] += na.x * w; acc[1] += na.y * w;
        acc[2] += na.z * w; acc[3] += na.w * w;
        acc[4] += nb.x * w; acc[5] += nb.y * w;
        acc[6] += nb.z * w; acc[7] += nb.w * w;
    }
#pragma unroll
    for (int j = 0; j < 8; j++) {
        int n = node0 + ng * 8 + j;
        if (n < N) {
            float v = fmaxf(acc[j], 0.0f);
            long long o = (long long)n * DIM + c;
            g_h0[o] = v;
            g_aggr[o] = v;
        }
    }
}

// ---------------- edge scatter: aggr[dst] += h0[src] (vector RED) -----------
__global__ void scatter_kernel(const void* __restrict__ edge, long long E) {
    long long t = (long long)blockIdx.x * blockDim.x + threadIdx.x;
    long long total = E * 16;
    if (t >= total) return;
    int is64 = g_is64;
    long long e = t >> 4;
    int q = (int)(t & 15);
    long long s = ld_idx(edge, e, is64);
    long long d = ld_idx(edge, E + e, is64);
    float4 v = *(const float4*)&g_h0[s * DIM + q * 4];
    float* dst = &g_aggr[d * DIM + q * 4];
    unsigned long long gaddr = (unsigned long long)__cvta_generic_to_global(dst);
    asm volatile("red.global.add.v4.f32 [%0], {%1, %2, %3, %4};"
                 :: "l"(gaddr), "f"(v.x), "f"(v.y), "f"(v.z), "f"(v.w)
                 : "memory");
}

// ------- h1 = relu(aggr @ gin_W + b); 32 nodes/block, reg-blocked ------------
__global__ __launch_bounds__(256) void gin_kernel(
        const float* __restrict__ W, const float* __restrict__ b, int N) {
    __shared__ float sW[DIM * DIM];        // 16 KB
    __shared__ float srow[32][DIM];        // 8 KB
    int tid = threadIdx.x;
    for (int i = tid; i < DIM * DIM; i += 256) sW[i] = W[i];
    int node0 = blockIdx.x * 32;
    int navail = N - node0; if (navail > 32) navail = 32;
    int tot4 = navail * (DIM / 4);
    long long abase = (long long)node0 * DIM;
    for (int i = tid; i < tot4; i += 256) {
        float4 v = *(const float4*)&g_aggr[abase + i * 4];
        *(float4*)&srow[i / 16][(i % 16) * 4] = v;
    }
    __syncthreads();
    int p  = tid >> 4;
    int c4 = (tid & 15) * 4;
    float acc0[4], acc1[4];
#pragma unroll
    for (int j = 0; j < 4; j++) { acc0[j] = b[c4 + j]; acc1[j] = acc0[j]; }
#pragma unroll 4
    for (int k0 = 0; k0 < DIM; k0 += 4) {
        float4 ra = *(const float4*)&srow[p][k0];
        float4 rb = *(const float4*)&srow[p + 16][k0];
#pragma unroll
        for (int kk = 0; kk < 4; kk++) {
            float4 wv = *(const float4*)&sW[(k0 + kk) * DIM + c4];
            float rav = (kk == 0) ? ra.x : (kk == 1) ? ra.y : (kk == 2) ? ra.z : ra.w;
            float rbv = (kk == 0) ? rb.x : (kk == 1) ? rb.y : (kk == 2) ? rb.z : rb.w;
            acc0[0] += rav * wv.x; acc0[1] += rav * wv.y;
            acc0[2] += rav * wv.z; acc0[3] += rav * wv.w;
            acc1[0] += rbv * wv.x; acc1[1] += rbv * wv.y;
            acc1[2] += rbv * wv.z; acc1[3] += rbv * wv.w;
        }
    }
    int nodeA = node0 + p, nodeB = node0 + p + 16;
    if (nodeA < N) {
        float4 o = make_float4(fmaxf(acc0[0], 0.f), fmaxf(acc0[1], 0.f),
                               fmaxf(acc0[2], 0.f), fmaxf(acc0[3], 0.f));
        *(float4*)&g_h1[(long long)nodeA * DIM + c4] = o;
    }
    if (nodeB < N) {
        float4 o = make_float4(fmaxf(acc1[0], 0.f), fmaxf(acc1[1], 0.f),
                               fmaxf(acc1[2], 0.f), fmaxf(acc1[3], 0.f));
        *(float4*)&g_h1[(long long)nodeB * DIM + c4] = o;
    }
}

// ------ LSTM cell, 16 graphs/block, packed float4 weights (MLP + coalesced) --
__global__ void lstm_kernel() {
    __shared__ float s[16 * 192];
    __shared__ float gates[16 * 256];
    int tid = threadIdx.x;
    int gb = blockIdx.x * 16;
    for (int i = tid; i < 16 * 192; i += 256) {
        int g = i / 192, k = i % 192;
        s[i] = (k < 128) ? g_qstar[(gb + g) * 128 + k]
                         : g_hs[(gb + g) * 64 + (k - 128)];
    }
    __syncthreads();
    int r = tid;
    float acc[16];
    float bsum = g_bias[r];
#pragma unroll
    for (int g = 0; g < 16; g++) acc[g] = bsum;
#pragma unroll 2
    for (int k4 = 0; k4 < 48; k4++) {
        float4 wv = *(const float4*)&g_W4[k4 * 1024 + r * 4];   // LDG.128 coalesced
#pragma unroll
        for (int g = 0; g < 16; g++) {
            float4 sv = *(const float4*)&s[g * 192 + k4 * 4];   // LDS.128 broadcast
            acc[g] = fmaf(wv.x, sv.x, acc[g]);
            acc[g] = fmaf(wv.y, sv.y, acc[g]);
            acc[g] = fmaf(wv.z, sv.z, acc[g]);
            acc[g] = fmaf(wv.w, sv.w, acc[g]);
        }
    }
#pragma unroll
    for (int g = 0; g < 16; g++) gates[g * 256 + r] = acc[g];
    __syncthreads();
    for (int cell = tid; cell < 16 * 64; cell += 256) {
        int g = cell >> 6, u = cell & 63;
        int gg = gb + g;
        float iv = gates[g * 256 + u];
        float fv = gates[g * 256 + 64 + u];
        float gv = gates[g * 256 + 128 + u];
        float ov = gates[g * 256 + 192 + u];
        float c_old = g_cs[gg * 64 + u];
        float c_new = sigm(fv) * c_old + sigm(iv) * tanhf(gv);
        float h_new = sigm(ov) * tanhf(c_new);
        g_cs[gg * 64 + u] = c_new;
        g_hs[gg * 64 + u] = h_new;
        g_qstar[gg * 128 + u] = h_new;
    }
}

// ----- per-graph softmax attention, single pass, 8 warps (shorter chain) -----
__global__ void attn_kernel() {
    __shared__ float qsh[DIM];
    __shared__ float rsh[8][DIM];
    __shared__ float dsh[8];
    __shared__ float msh[8];
    int g = blockIdx.x;
    int tid = threadIdx.x;
    int warp = tid >> 5, lane = tid & 31;
    if (tid < DIM) qsh[tid] = g_hs[g * DIM + tid];
    __syncthreads();
    int s0 = g_start[g], s1 = g_start[g + 1];
    float qa = qsh[2 * lane], qb = qsh[2 * lane + 1];
    float m = -1e30f, d = 0.0f, rx = 0.0f, ry = 0.0f;
    for (int n = s0 + warp; n < s1; n += 8) {
        float2 hv = *(const float2*)&g_h1[(long long)n * DIM + 2 * lane];
        float p = hv.x * qa + hv.y * qb;
#pragma unroll
        for (int off = 16; off > 0; off >>= 1) p += __shfl_xor_sync(0xFFFFFFFF, p, off);
        float mn = fmaxf(m, p);
        float sc = __expf(m - mn);
        float wt = __expf(p - mn);
        d  = d * sc + wt;
        rx = rx * sc + wt * hv.x;
        ry = ry * sc + wt * hv.y;
        m = mn;
    }
    rsh[warp][2 * lane]     = rx;
    rsh[warp][2 * lane + 1] = ry;
    if (lane == 0) { dsh[warp] = d; msh[warp] = m; }
    __syncthreads();
    if (tid < DIM) {
        float gm = -1e30f;
#pragma unroll
        for (int w = 0; w < 8; w++) gm = fmaxf(gm, msh[w]);
        float r = 0.0f, den = 0.0f;
#pragma unroll
        for (int w = 0; w < 8; w++) {
            float sc = (msh[w] > -1e29f) ? __expf(msh[w] - gm) : 0.0f;
            r   += rsh[w][tid] * sc;
            den += dsh[w] * sc;
        }
        if (den == 0.0f) den = 1.0f;
        g_qstar[g * 128 + DIM + tid] = r / den;
    }
}

// ---------------- head: out = relu(q_star@lin1+b1) @ lin2 + b2 --------------
__global__ void head_kernel(const float* __restrict__ lin1_W,
                            const float* __restrict__ lin1_b,
                            const float* __restrict__ lin2_W,
                            const float* __restrict__ lin2_b,
                            float* __restrict__ out) {
    __shared__ float qs[128];
    __shared__ float red[64];
    int g = blockIdx.x;
    int t = threadIdx.x;
    qs[t] = g_qstar[g * 128 + t];
    qs[t + 64] = g_qstar[g * 128 + t + 64];
    __syncthreads();
    float acc = lin1_b[t];
#pragma unroll 8
    for (int k = 0; k < 128; k++) acc += qs[k] * lin1_W[k * 64 + t];
    acc = fmaxf(acc, 0.0f);
    red[t] = acc * lin2_W[t];
    __syncthreads();
    if (t < 32) {
        float v = red[t] + red[t + 32];
#pragma unroll
        for (int off = 16; off > 0; off >>= 1) v += __shfl_xor_sync(0xFFFFFFFF, v, off);
        if (t == 0) out[g] = v + lin2_b[0];
    }
}

// ---------------- launch ------------------------------------------------------
extern "C" void kernel_launch(void* const* d_in, const int* in_sizes, int n_in,
                              void* d_out, int out_size) {
    const float* x      = (const float*)d_in[0];
    const void*  edge   = d_in[1];
    const void*  batch  = d_in[2];
    const float* lin0_W = (const float*)d_in[3];
    const float* lin0_b = (const float*)d_in[4];
    const float* gin_W  = (const float*)d_in[5];
    const float* gin_b  = (const float*)d_in[6];
    const float* W_ih   = (const float*)d_in[7];
    const float* W_hh   = (const float*)d_in[8];
    const float* b_ih   = (const float*)d_in[9];
    const float* b_hh   = (const float*)d_in[10];
    const float* lin1_W = (const float*)d_in[11];
    const float* lin1_b = (const float*)d_in[12];
    const float* lin2_W = (const float*)d_in[13];
    const float* lin2_b = (const float*)d_in[14];
    float* out = (float*)d_out;

    int N = in_sizes[0] / INDIM;
    long long E = (long long)in_sizes[1] / 2;

    prep_kernel<<<(NGRAPH * 2 * DIM + 255) / 256, 256>>>(batch, N, W_ih, W_hh, b_ih, b_hh);
    offsets_kernel<<<(N + 255) / 256, 256>>>(batch, N);
    lin0_kernel<<<(N + 31) / 32, 256>>>(x, lin0_W, lin0_b, N);
    long long sc_threads = E * 16;
    scatter_kernel<<<(unsigned)((sc_threads + 255) / 256), 256>>>(edge, E);
    gin_kernel<<<(N + 31) / 32, 256>>>(gin_W, gin_b, N);
    for (int step = 0; step < 3; step++) {
        lstm_kernel<<<NGRAPH / 16, 256>>>();
        attn_kernel<<<NGRAPH, 256>>>();
    }
    head_kernel<<<NGRAPH, 64>>>(lin1_W, lin1_b, lin2_W, lin2_b, out);
}